// round 4
// baseline (speedup 1.0000x reference)
#include <cuda_runtime.h>
#include <math.h>

#define BATCH 4
#define SEQ   512
#define HD    768
#define DD    24
#define MMDIM 96
#define OO    768
#define ROWS  (BATCH*SEQ)       // 2048
#define XCOLS (3*HD)            // 2304

typedef unsigned long long ull;

// ---------------- scratch (no allocations allowed) ----------------
__device__ float g_Zj[ROWS*DD];
__device__ float g_Zi[ROWS*DD];
__device__ float g_tjb[ROWS*MMDIM];
__device__ float g_ti[ROWS*MMDIM];
__device__ float g_probs[(long)BATCH*SEQ*SEQ];
__device__ float g_ctx[(long)ROWS*HD];
__device__ float g_mhid[(long)ROWS*OO];

// ---------------- packed f32x2 helpers ----------------
__device__ __forceinline__ ull pk2(float x) {
    ull r; asm("mov.b64 %0, {%1, %1};" : "=l"(r) : "f"(x)); return r;
}
__device__ __forceinline__ void fma2(ull &d, ull a, ull b) {
    asm("fma.rn.f32x2 %0, %1, %2, %0;" : "+l"(d) : "l"(a), "l"(b));
}
__device__ __forceinline__ float2 up2(ull v) {
    float2 r; asm("mov.b64 {%0, %1}, %2;" : "=f"(r.x), "=f"(r.y) : "l"(v)); return r;
}

// ---------------- small generic SGEMM, z-batched over pointer pairs ----------------
__global__ __launch_bounds__(256)
void sgemm_small2(const float* __restrict__ A0, const float* __restrict__ B0,
                  float* __restrict__ C0, const float* __restrict__ bias0,
                  const float* __restrict__ A1, const float* __restrict__ B1,
                  float* __restrict__ C1, const float* __restrict__ bias1,
                  int M, int N, int K, int lda, int ldb, int ldc)
{
    __shared__ float As[16][64];
    __shared__ float Bs[16][64];
    const float* A = blockIdx.z ? A1 : A0;
    const float* B = blockIdx.z ? B1 : B0;
    float*       C = blockIdx.z ? C1 : C0;
    const float* bias = blockIdx.z ? bias1 : bias0;

    const int tid = threadIdx.x;
    const int tx = tid & 15, ty = tid >> 4;
    const int row0 = blockIdx.y * 64;
    const int col0 = blockIdx.x * 64;

    float acc[4][4] = {};
    for (int k0 = 0; k0 < K; k0 += 16) {
        #pragma unroll
        for (int u = 0; u < 4; ++u) {
            int t = tid + u * 256;
            int r = t >> 4, kk = t & 15;
            int gr = row0 + r, gk = k0 + kk;
            float v = 0.f;
            if (gr < M && gk < K) v = A[(long)gr * lda + gk];
            As[kk][r] = v;
        }
        #pragma unroll
        for (int u = 0; u < 4; ++u) {
            int t = tid + u * 256;
            int kk = t >> 6, n = t & 63;
            int gk = k0 + kk, gn = col0 + n;
            float v = 0.f;
            if (gk < K && gn < N) v = B[(long)gk * ldb + gn];
            Bs[kk][n] = v;
        }
        __syncthreads();
        #pragma unroll
        for (int kk = 0; kk < 16; ++kk) {
            float4 a4 = *(const float4*)&As[kk][ty * 4];
            float4 b4 = *(const float4*)&Bs[kk][tx * 4];
            float a[4] = {a4.x, a4.y, a4.z, a4.w};
            float b[4] = {b4.x, b4.y, b4.z, b4.w};
            #pragma unroll
            for (int i = 0; i < 4; ++i)
                #pragma unroll
                for (int j = 0; j < 4; ++j)
                    acc[i][j] = fmaf(a[i], b[j], acc[i][j]);
        }
        __syncthreads();
    }
    #pragma unroll
    for (int i = 0; i < 4; ++i) {
        int r = row0 + ty * 4 + i;
        if (r >= M) continue;
        #pragma unroll
        for (int j = 0; j < 4; ++j) {
            int c = col0 + tx * 4 + j;
            if (c >= N) continue;
            float v = acc[i][j];
            if (bias) v += bias[c];
            C[(long)r * ldc + c] = v;
        }
    }
}

// ---------------- 64x64 FFMA2 GEMM: 256 threads, KT=32, double-buffered ----------------
// Microtile 4x4. Exact-multiple dims, unguarded.
// AMODE 0: A pointer. AMODE 1: A = [ctx | Hj | ctx*Hj] generated on the fly.
template<int AMODE, bool BIAS, bool RELU, bool SCALE>
__global__ __launch_bounds__(256)
void gemm256(const float* __restrict__ A, const float* __restrict__ B,
             float* __restrict__ C, int K, int lda, int ldb, int ldc,
             const float* __restrict__ bias, const float* __restrict__ alpha_ptr,
             long sA, long sB, long sC,
             const float* __restrict__ Actx, const float* __restrict__ Ahj)
{
    __shared__ float As[2][32][68];
    __shared__ float Bs[2][32][68];

    const int bz = blockIdx.z;
    if (AMODE == 0) A += (long)bz * sA;
    B += (long)bz * sB;  C += (long)bz * sC;

    const int tid = threadIdx.x;
    const int tx = tid & 15, ty = tid >> 4;
    const int row0 = blockIdx.y * 64;
    const int col0 = blockIdx.x * 64;

    // loader indices
    const int ar = tid >> 3, akc = tid & 7;    // A: (row, k-chunk). lin u-phase adds 32 rows
    const int bk = tid >> 4, bn4 = tid & 15;   // B: (k row, col-chunk). u-phase adds 16 k

    ull acc[4][2];
    #pragma unroll
    for (int i = 0; i < 4; ++i) { acc[i][0] = 0ull; acc[i][1] = 0ull; }

    float4 pa[2], pb[2];

    auto loadA = [&](int kt) {
        #pragma unroll
        for (int u = 0; u < 2; ++u) {
            int r = ar + u * 32;
            int gk = kt + akc * 4;
            if (AMODE == 0) {
                pa[u] = *(const float4*)&A[(long)(row0 + r) * lda + gk];
            } else {
                long ridx = (long)(row0 + r) * HD;
                if (gk < HD) {
                    pa[u] = *(const float4*)&Actx[ridx + gk];
                } else if (gk < 2 * HD) {
                    pa[u] = *(const float4*)&Ahj[ridx + gk - HD];
                } else {
                    float4 c4 = *(const float4*)&Actx[ridx + gk - 2 * HD];
                    float4 h4 = *(const float4*)&Ahj[ridx + gk - 2 * HD];
                    pa[u].x = c4.x * h4.x; pa[u].y = c4.y * h4.y;
                    pa[u].z = c4.z * h4.z; pa[u].w = c4.w * h4.w;
                }
            }
        }
    };
    auto loadB = [&](int kt) {
        #pragma unroll
        for (int u = 0; u < 2; ++u)
            pb[u] = *(const float4*)&B[(long)(kt + bk + u * 16) * ldb + col0 + bn4 * 4];
    };
    auto storeTiles = [&](int buf) {
        #pragma unroll
        for (int u = 0; u < 2; ++u) {
            int r = ar + u * 32;
            As[buf][akc * 4 + 0][r] = pa[u].x;
            As[buf][akc * 4 + 1][r] = pa[u].y;
            As[buf][akc * 4 + 2][r] = pa[u].z;
            As[buf][akc * 4 + 3][r] = pa[u].w;
            *(float4*)&Bs[buf][bk + u * 16][bn4 * 4] = pb[u];
        }
    };

    loadA(0); loadB(0);
    storeTiles(0);
    __syncthreads();

    int cur = 0;
    for (int kt = 0; kt < K; kt += 32) {
        const bool more = (kt + 32) < K;
        if (more) { loadA(kt + 32); loadB(kt + 32); }

        #pragma unroll
        for (int kk = 0; kk < 32; ++kk) {
            float4 a4 = *(const float4*)&As[cur][kk][ty * 4];
            ulonglong2 bl = *(const ulonglong2*)&Bs[cur][kk][tx * 4];
            ull ap[4];
            ap[0] = pk2(a4.x); ap[1] = pk2(a4.y); ap[2] = pk2(a4.z); ap[3] = pk2(a4.w);
            #pragma unroll
            for (int i = 0; i < 4; ++i) {
                fma2(acc[i][0], ap[i], bl.x);
                fma2(acc[i][1], ap[i], bl.y);
            }
        }
        if (more) {
            storeTiles(cur ^ 1);
            __syncthreads();
            cur ^= 1;
        }
    }

    float alpha = 1.f;
    if (SCALE) alpha = *alpha_ptr;

    float4 bv;
    if (BIAS) bv = *(const float4*)&bias[col0 + tx * 4];

    #pragma unroll
    for (int i = 0; i < 4; ++i) {
        int r = row0 + ty * 4 + i;
        int c = col0 + tx * 4;
        float2 p0 = up2(acc[i][0]);
        float2 p1 = up2(acc[i][1]);
        float4 v = make_float4(p0.x, p0.y, p1.x, p1.y);
        if (BIAS) { v.x += bv.x; v.y += bv.y; v.z += bv.z; v.w += bv.w; }
        if (RELU) {
            v.x = fmaxf(v.x, 0.f); v.y = fmaxf(v.y, 0.f);
            v.z = fmaxf(v.z, 0.f); v.w = fmaxf(v.w, 0.f);
        }
        v.x *= alpha; v.y *= alpha; v.z *= alpha; v.w *= alpha;
        *(float4*)&C[(long)r * ldc + c] = v;
    }
}

// ---------------- fused pairwise logits + softmax (FFMA2) ----------------
// One block (128 thr) per p-row. q-tile 128, microtile 8q x 12m, K=48 in 2 phases of 24.
__global__ __launch_bounds__(128)
void pairwise_kernel(const float* __restrict__ Zj, const float* __restrict__ Zi,
                     const float* __restrict__ tjb, const float* __restrict__ ti,
                     const float* __restrict__ Ws1, const float* __restrict__ ws2,
                     const float* __restrict__ bs2, const int* __restrict__ attn_mask,
                     float* __restrict__ probs)
{
    __shared__ float Wc_s[48][96];
    __shared__ float Gs[24][128];
    __shared__ float Zis[128][25];
    __shared__ float logits_s[512];
    __shared__ float Zjp_s[24];
    __shared__ float tjb_s[96];
    __shared__ float ws2_s[96];
    __shared__ float red_s[8];

    const int tid = threadIdx.x;
    const int tx = tid & 7;
    const int ty = tid >> 3;
    const int pg = blockIdx.x;
    const int b = pg >> 9;

    for (int idx = tid; idx < 48 * 96; idx += 128)
        (&Wc_s[0][0])[idx] = Ws1[48 * 96 + idx];
    if (tid < 24) Zjp_s[tid] = Zj[pg * 24 + tid];
    if (tid < 96) { tjb_s[tid] = tjb[pg * 96 + tid]; ws2_s[tid] = ws2[tid]; }
    __syncthreads();

    #pragma unroll 1
    for (int qt = 0; qt < 4; ++qt) {
        const int q0 = qt * 128;
        for (int idx = tid; idx < 128 * 24; idx += 128) {
            int q = idx / 24, d = idx - q * 24;
            Zis[q][d] = Zi[((long)(b * 512 + q0 + q)) * 24 + d];
        }
        __syncthreads();

        ull acc[8][6];
        #pragma unroll
        for (int i = 0; i < 8; ++i)
            #pragma unroll
            for (int j = 0; j < 6; ++j) acc[i][j] = 0ull;

        #pragma unroll 1
        for (int ph = 0; ph < 2; ++ph) {
            for (int idx = tid; idx < 24 * 128; idx += 128) {
                int k = idx >> 7, q = idx & 127;
                float zj = Zjp_s[k], zi = Zis[q][k];
                Gs[k][q] = ph ? fabsf(zj - zi) : zj * zi;
            }
            __syncthreads();
            const int kbase = ph * 24;
            #pragma unroll
            for (int k = 0; k < 24; ++k) {
                float4 g0 = *(const float4*)&Gs[k][ty * 8];
                float4 g1 = *(const float4*)&Gs[k][ty * 8 + 4];
                ulonglong2 w0 = *(const ulonglong2*)&Wc_s[kbase + k][tx * 12];
                ulonglong2 w1 = *(const ulonglong2*)&Wc_s[kbase + k][tx * 12 + 4];
                ulonglong2 w2 = *(const ulonglong2*)&Wc_s[kbase + k][tx * 12 + 8];
                ull gp[8];
                gp[0] = pk2(g0.x); gp[1] = pk2(g0.y); gp[2] = pk2(g0.z); gp[3] = pk2(g0.w);
                gp[4] = pk2(g1.x); gp[5] = pk2(g1.y); gp[6] = pk2(g1.z); gp[7] = pk2(g1.w);
                #pragma unroll
                for (int i = 0; i < 8; ++i) {
                    fma2(acc[i][0], gp[i], w0.x);
                    fma2(acc[i][1], gp[i], w0.y);
                    fma2(acc[i][2], gp[i], w1.x);
                    fma2(acc[i][3], gp[i], w1.y);
                    fma2(acc[i][4], gp[i], w2.x);
                    fma2(acc[i][5], gp[i], w2.y);
                }
            }
            __syncthreads();
        }

        #pragma unroll
        for (int i = 0; i < 8; ++i) {
            int q = ty * 8 + i;
            const float4* tirow = (const float4*)&ti[((long)(b * 512 + q0 + q)) * 96 + tx * 12];
            float4 t0 = tirow[0], t1 = tirow[1], t2 = tirow[2];
            float tv[12] = {t0.x, t0.y, t0.z, t0.w, t1.x, t1.y, t1.z, t1.w,
                            t2.x, t2.y, t2.z, t2.w};
            float s = 0.f;
            #pragma unroll
            for (int j = 0; j < 6; ++j) {
                int m = tx * 12 + 2 * j;
                float2 a = up2(acc[i][j]);
                float h0 = fmaxf(a.x + tjb_s[m] + tv[2 * j], 0.f);
                float h1 = fmaxf(a.y + tjb_s[m + 1] + tv[2 * j + 1], 0.f);
                s = fmaf(h0, ws2_s[m], s);
                s = fmaf(h1, ws2_s[m + 1], s);
            }
            s += __shfl_xor_sync(0xffffffffu, s, 1);
            s += __shfl_xor_sync(0xffffffffu, s, 2);
            s += __shfl_xor_sync(0xffffffffu, s, 4);
            if (tx == 0) logits_s[q0 + q] = s;
        }
    }
    __syncthreads();

    const float bs2v = *bs2;
    #pragma unroll
    for (int q = tid; q < 512; q += 128) {
        float mv = (float)attn_mask[b * 512 + q];
        logits_s[q] += bs2v + (1.f - mv) * (-3.402823466e38f);
    }
    __syncthreads();

    const int wid = tid >> 5, lane = tid & 31;
    float lmax = -INFINITY;
    #pragma unroll
    for (int q = tid; q < 512; q += 128) lmax = fmaxf(lmax, logits_s[q]);
    #pragma unroll
    for (int o = 16; o > 0; o >>= 1) lmax = fmaxf(lmax, __shfl_xor_sync(0xffffffffu, lmax, o));
    if (lane == 0) red_s[wid] = lmax;
    __syncthreads();
    lmax = fmaxf(fmaxf(red_s[0], red_s[1]), fmaxf(red_s[2], red_s[3]));

    float lsum = 0.f;
    float ev[4];
    #pragma unroll
    for (int u = 0; u < 4; ++u) {
        int q = tid + u * 128;
        ev[u] = __expf(logits_s[q] - lmax);
        lsum += ev[u];
    }
    #pragma unroll
    for (int o = 16; o > 0; o >>= 1) lsum += __shfl_xor_sync(0xffffffffu, lsum, o);
    if (lane == 0) red_s[4 + wid] = lsum;
    __syncthreads();
    const float inv = 1.f / (red_s[4] + red_s[5] + red_s[6] + red_s[7]);
    #pragma unroll
    for (int u = 0; u < 4; ++u) {
        int q = tid + u * 128;
        probs[(long)pg * 512 + q] = ev[u] * inv;
    }
}

// ---------------- launch ----------------
extern "C" void kernel_launch(void* const* d_in, const int* in_sizes, int n_in,
                              void* d_out, int out_size)
{
    const float* Hj   = (const float*)d_in[0];
    const float* Hi   = (const float*)d_in[1];
    const float* Wpj  = (const float*)d_in[2];
    const float* Wpi  = (const float*)d_in[3];
    const float* Ws1  = (const float*)d_in[4];
    const float* bs1  = (const float*)d_in[5];
    const float* ws2  = (const float*)d_in[6];
    const float* bs2  = (const float*)d_in[7];
    const float* Wv1  = (const float*)d_in[8];
    const float* bv1  = (const float*)d_in[9];
    const float* Wv2  = (const float*)d_in[10];
    const float* bv2  = (const float*)d_in[11];
    const float* alpha= (const float*)d_in[12];
    const int*   mask = (const int*)d_in[13];
    float* out = (float*)d_out;

    float *Zj, *Zi, *tjb, *ti, *probs, *ctx, *mhid;
    cudaGetSymbolAddress((void**)&Zj, g_Zj);
    cudaGetSymbolAddress((void**)&Zi, g_Zi);
    cudaGetSymbolAddress((void**)&tjb, g_tjb);
    cudaGetSymbolAddress((void**)&ti, g_ti);
    cudaGetSymbolAddress((void**)&probs, g_probs);
    cudaGetSymbolAddress((void**)&ctx, g_ctx);
    cudaGetSymbolAddress((void**)&mhid, g_mhid);

    // Zj = H_j @ Wpj ; Zi = H_i @ Wpi   (2048 x 24, K=768), batched
    sgemm_small2<<<dim3(1, ROWS/64, 2), 256>>>(
        Hj, Wpj, Zj, nullptr, Hi, Wpi, Zi, nullptr,
        ROWS, DD, HD, HD, DD, DD);

    // tjb = Zj @ Ws1[0:24] + bs1 ; ti = Zi @ Ws1[24:48]   (2048 x 96, K=24), batched
    sgemm_small2<<<dim3(2, ROWS/64, 2), 256>>>(
        Zj, Ws1, tjb, bs1, Zi, Ws1 + DD * MMDIM, ti, nullptr,
        ROWS, MMDIM, DD, DD, MMDIM, MMDIM);

    // fused pairwise logits + softmax -> probs
    pairwise_kernel<<<ROWS, 128>>>(Zj, Zi, tjb, ti, Ws1, ws2, bs2, mask, probs);

    // ctx = probs @ H_i   (batched 4x: 512 x 768, K=512)
    gemm256<0,false,false,false><<<dim3(HD/64, SEQ/64, BATCH), 256>>>(
        probs, Hi, ctx, SEQ, SEQ, HD, HD, nullptr, nullptr,
        (long)SEQ*SEQ, (long)SEQ*HD, (long)SEQ*HD, nullptr, nullptr);

    // mhid = relu([ctx|Hj|ctx*Hj] @ Wv1 + bv1)   (2048 x 768, K=2304; X fused)
    gemm256<1,true,true,false><<<dim3(OO/64, ROWS/64, 1), 256>>>(
        nullptr, Wv1, mhid, XCOLS, 0, OO, OO, bv1, nullptr,
        0, 0, 0, ctx, Hj);

    // out = alpha * (mhid @ Wv2 + bv2)   (2048 x 768, K=768)
    gemm256<0,true,false,true><<<dim3(HD/64, ROWS/64, 1), 256>>>(
        mhid, Wv2, out, OO, OO, HD, HD, bv2, alpha,
        0, 0, 0, nullptr, nullptr);
}

// round 5
// speedup vs baseline: 1.0014x; 1.0014x over previous
#include <cuda_runtime.h>
#include <math.h>

#define BATCH 4
#define SEQ   512
#define HD    768
#define DD    24
#define MMDIM 96
#define OO    768
#define ROWS  (BATCH*SEQ)       // 2048
#define XCOLS (3*HD)            // 2304

typedef unsigned long long ull;

// ---------------- scratch (no allocations allowed) ----------------
__device__ float g_Zj[ROWS*DD];
__device__ float g_Zi[ROWS*DD];
__device__ float g_tjb[ROWS*MMDIM];
__device__ float g_ti[ROWS*MMDIM];
__device__ float g_probs[(long)BATCH*SEQ*SEQ];
__device__ float g_ctx[(long)ROWS*HD];
__device__ float g_mhid[(long)ROWS*OO];

// ---------------- packed f32x2 helpers ----------------
__device__ __forceinline__ ull pk2(float x) {
    ull r; asm("mov.b64 %0, {%1, %1};" : "=l"(r) : "f"(x)); return r;
}
__device__ __forceinline__ void fma2(ull &d, ull a, ull b) {
    asm("fma.rn.f32x2 %0, %1, %2, %0;" : "+l"(d) : "l"(a), "l"(b));
}
__device__ __forceinline__ float2 up2(ull v) {
    float2 r; asm("mov.b64 {%0, %1}, %2;" : "=f"(r.x), "=f"(r.y) : "l"(v)); return r;
}

// ---------------- small generic SGEMM, z-batched over pointer pairs ----------------
__global__ __launch_bounds__(256)
void sgemm_small2(const float* __restrict__ A0, const float* __restrict__ B0,
                  float* __restrict__ C0, const float* __restrict__ bias0,
                  const float* __restrict__ A1, const float* __restrict__ B1,
                  float* __restrict__ C1, const float* __restrict__ bias1,
                  int M, int N, int K, int lda, int ldb, int ldc)
{
    __shared__ float As[16][64];
    __shared__ float Bs[16][64];
    const float* A = blockIdx.z ? A1 : A0;
    const float* B = blockIdx.z ? B1 : B0;
    float*       C = blockIdx.z ? C1 : C0;
    const float* bias = blockIdx.z ? bias1 : bias0;

    const int tid = threadIdx.x;
    const int tx = tid & 15, ty = tid >> 4;
    const int row0 = blockIdx.y * 64;
    const int col0 = blockIdx.x * 64;

    float acc[4][4] = {};
    for (int k0 = 0; k0 < K; k0 += 16) {
        #pragma unroll
        for (int u = 0; u < 4; ++u) {
            int t = tid + u * 256;
            int r = t >> 4, kk = t & 15;
            int gr = row0 + r, gk = k0 + kk;
            float v = 0.f;
            if (gr < M && gk < K) v = A[(long)gr * lda + gk];
            As[kk][r] = v;
        }
        #pragma unroll
        for (int u = 0; u < 4; ++u) {
            int t = tid + u * 256;
            int kk = t >> 6, n = t & 63;
            int gk = k0 + kk, gn = col0 + n;
            float v = 0.f;
            if (gk < K && gn < N) v = B[(long)gk * ldb + gn];
            Bs[kk][n] = v;
        }
        __syncthreads();
        #pragma unroll
        for (int kk = 0; kk < 16; ++kk) {
            float4 a4 = *(const float4*)&As[kk][ty * 4];
            float4 b4 = *(const float4*)&Bs[kk][tx * 4];
            float a[4] = {a4.x, a4.y, a4.z, a4.w};
            float b[4] = {b4.x, b4.y, b4.z, b4.w};
            #pragma unroll
            for (int i = 0; i < 4; ++i)
                #pragma unroll
                for (int j = 0; j < 4; ++j)
                    acc[i][j] = fmaf(a[i], b[j], acc[i][j]);
        }
        __syncthreads();
    }
    #pragma unroll
    for (int i = 0; i < 4; ++i) {
        int r = row0 + ty * 4 + i;
        if (r >= M) continue;
        #pragma unroll
        for (int j = 0; j < 4; ++j) {
            int c = col0 + tx * 4 + j;
            if (c >= N) continue;
            float v = acc[i][j];
            if (bias) v += bias[c];
            C[(long)r * ldc + c] = v;
        }
    }
}

// ---------------- gemmv3: 128x64 tile, 128 threads, 8x8 microtile, double-buffered ----------------
// Balanced pipes: per kk/thread 4 LDS.128 vs 32 fma2 (crossbar 16W cyc == fma 16W cyc).
// Exact-multiple dims, unguarded. AMODE 0: plain A. AMODE 1: A=[ctx|Hj|ctx*Hj] on the fly.
template<int AMODE, bool BIAS, bool RELU, bool SCALE>
__global__ __launch_bounds__(128)
void gemmv3(const float* __restrict__ A, const float* __restrict__ B,
            float* __restrict__ C, int K, int lda, int ldb, int ldc,
            const float* __restrict__ bias, const float* __restrict__ alpha_ptr,
            long sA, long sB, long sC,
            const float* __restrict__ Actx, const float* __restrict__ Ahj)
{
    __shared__ float As[2][16][132];   // [k][row], 128 rows + pad
    __shared__ float Bs[2][16][68];    // [k][col], 64 cols + pad

    const int bz = blockIdx.z;
    if (AMODE == 0) A += (long)bz * sA;
    B += (long)bz * sB;  C += (long)bz * sC;

    const int tid = threadIdx.x;
    const int tx = tid & 7;            // col group: 8 cols each
    const int ty = tid >> 3;           // row group: 8 rows each (0..15)
    const int row0 = blockIdx.y * 128;
    const int col0 = blockIdx.x * 64;

    // loader indices
    const int ar4 = tid >> 2, akc = tid & 3;   // A: 32 rows/pass x 4 k-chunks
    const int bk = tid >> 4, bn4 = tid & 15;   // B: 8 k-rows/pass x 16 col-chunks

    ull acc[8][4];
    #pragma unroll
    for (int i = 0; i < 8; ++i)
        #pragma unroll
        for (int j = 0; j < 4; ++j) acc[i][j] = 0ull;

    float4 pa[4], pb[2];

    auto loadA = [&](int kt) {
        const int gk = kt + akc * 4;
        #pragma unroll
        for (int u = 0; u < 4; ++u) {
            int r = row0 + ar4 + u * 32;
            if (AMODE == 0) {
                pa[u] = *(const float4*)&A[(long)r * lda + gk];
            } else {
                long ridx = (long)r * HD;
                if (gk < HD) {
                    pa[u] = *(const float4*)&Actx[ridx + gk];
                } else if (gk < 2 * HD) {
                    pa[u] = *(const float4*)&Ahj[ridx + gk - HD];
                } else {
                    float4 c4 = *(const float4*)&Actx[ridx + gk - 2 * HD];
                    float4 h4 = *(const float4*)&Ahj[ridx + gk - 2 * HD];
                    pa[u].x = c4.x * h4.x; pa[u].y = c4.y * h4.y;
                    pa[u].z = c4.z * h4.z; pa[u].w = c4.w * h4.w;
                }
            }
        }
    };
    auto loadB = [&](int kt) {
        #pragma unroll
        for (int u = 0; u < 2; ++u)
            pb[u] = *(const float4*)&B[(long)(kt + bk + u * 8) * ldb + col0 + bn4 * 4];
    };
    auto storeTiles = [&](int buf) {
        #pragma unroll
        for (int u = 0; u < 4; ++u) {
            int r = ar4 + u * 32;
            As[buf][akc * 4 + 0][r] = pa[u].x;
            As[buf][akc * 4 + 1][r] = pa[u].y;
            As[buf][akc * 4 + 2][r] = pa[u].z;
            As[buf][akc * 4 + 3][r] = pa[u].w;
        }
        #pragma unroll
        for (int u = 0; u < 2; ++u)
            *(float4*)&Bs[buf][bk + u * 8][bn4 * 4] = pb[u];
    };

    loadA(0); loadB(0);
    storeTiles(0);
    __syncthreads();

    int cur = 0;
    for (int kt = 0; kt < K; kt += 16) {
        const bool more = (kt + 16) < K;
        if (more) { loadA(kt + 16); loadB(kt + 16); }

        #pragma unroll
        for (int kk = 0; kk < 16; ++kk) {
            float4 a0 = *(const float4*)&As[cur][kk][ty * 8];
            float4 a1 = *(const float4*)&As[cur][kk][ty * 8 + 4];
            ulonglong2 b0 = *(const ulonglong2*)&Bs[cur][kk][tx * 8];
            ulonglong2 b1 = *(const ulonglong2*)&Bs[cur][kk][tx * 8 + 4];
            ull ap[8];
            ap[0] = pk2(a0.x); ap[1] = pk2(a0.y); ap[2] = pk2(a0.z); ap[3] = pk2(a0.w);
            ap[4] = pk2(a1.x); ap[5] = pk2(a1.y); ap[6] = pk2(a1.z); ap[7] = pk2(a1.w);
            #pragma unroll
            for (int i = 0; i < 8; ++i) {
                fma2(acc[i][0], ap[i], b0.x);
                fma2(acc[i][1], ap[i], b0.y);
                fma2(acc[i][2], ap[i], b1.x);
                fma2(acc[i][3], ap[i], b1.y);
            }
        }
        if (more) {
            storeTiles(cur ^ 1);
            __syncthreads();
            cur ^= 1;
        }
    }

    float alpha = 1.f;
    if (SCALE) alpha = *alpha_ptr;

    float4 bv0, bv1;
    if (BIAS) {
        bv0 = *(const float4*)&bias[col0 + tx * 8];
        bv1 = *(const float4*)&bias[col0 + tx * 8 + 4];
    }

    #pragma unroll
    for (int i = 0; i < 8; ++i) {
        int r = row0 + ty * 8 + i;
        #pragma unroll
        for (int half = 0; half < 2; ++half) {
            int c = col0 + tx * 8 + half * 4;
            float2 p0 = up2(acc[i][half * 2 + 0]);
            float2 p1 = up2(acc[i][half * 2 + 1]);
            float4 v = make_float4(p0.x, p0.y, p1.x, p1.y);
            if (BIAS) {
                float4 bv = half ? bv1 : bv0;
                v.x += bv.x; v.y += bv.y; v.z += bv.z; v.w += bv.w;
            }
            if (RELU) {
                v.x = fmaxf(v.x, 0.f); v.y = fmaxf(v.y, 0.f);
                v.z = fmaxf(v.z, 0.f); v.w = fmaxf(v.w, 0.f);
            }
            v.x *= alpha; v.y *= alpha; v.z *= alpha; v.w *= alpha;
            *(float4*)&C[(long)r * ldc + c] = v;
        }
    }
}

// ---------------- fused pairwise logits + softmax (FFMA2) — R3 version ----------------
__global__ __launch_bounds__(128)
void pairwise_kernel(const float* __restrict__ Zj, const float* __restrict__ Zi,
                     const float* __restrict__ tjb, const float* __restrict__ ti,
                     const float* __restrict__ Ws1, const float* __restrict__ ws2,
                     const float* __restrict__ bs2, const int* __restrict__ attn_mask,
                     float* __restrict__ probs)
{
    __shared__ float Wc_s[48][96];
    __shared__ float Gs[24][128];
    __shared__ float Zis[128][25];
    __shared__ float logits_s[512];
    __shared__ float Zjp_s[24];
    __shared__ float tjb_s[96];
    __shared__ float ws2_s[96];
    __shared__ float red_s[8];

    const int tid = threadIdx.x;
    const int tx = tid & 7;
    const int ty = tid >> 3;
    const int pg = blockIdx.x;
    const int b = pg >> 9;

    for (int idx = tid; idx < 48 * 96; idx += 128)
        (&Wc_s[0][0])[idx] = Ws1[48 * 96 + idx];
    if (tid < 24) Zjp_s[tid] = Zj[pg * 24 + tid];
    if (tid < 96) { tjb_s[tid] = tjb[pg * 96 + tid]; ws2_s[tid] = ws2[tid]; }
    __syncthreads();

    #pragma unroll 1
    for (int qt = 0; qt < 4; ++qt) {
        const int q0 = qt * 128;
        for (int idx = tid; idx < 128 * 24; idx += 128) {
            int q = idx / 24, d = idx - q * 24;
            Zis[q][d] = Zi[((long)(b * 512 + q0 + q)) * 24 + d];
        }
        __syncthreads();

        ull acc[8][6];
        #pragma unroll
        for (int i = 0; i < 8; ++i)
            #pragma unroll
            for (int j = 0; j < 6; ++j) acc[i][j] = 0ull;

        #pragma unroll 1
        for (int ph = 0; ph < 2; ++ph) {
            for (int idx = tid; idx < 24 * 128; idx += 128) {
                int k = idx >> 7, q = idx & 127;
                float zj = Zjp_s[k], zi = Zis[q][k];
                Gs[k][q] = ph ? fabsf(zj - zi) : zj * zi;
            }
            __syncthreads();
            const int kbase = ph * 24;
            #pragma unroll
            for (int k = 0; k < 24; ++k) {
                float4 g0 = *(const float4*)&Gs[k][ty * 8];
                float4 g1 = *(const float4*)&Gs[k][ty * 8 + 4];
                ulonglong2 w0 = *(const ulonglong2*)&Wc_s[kbase + k][tx * 12];
                ulonglong2 w1 = *(const ulonglong2*)&Wc_s[kbase + k][tx * 12 + 4];
                ulonglong2 w2 = *(const ulonglong2*)&Wc_s[kbase + k][tx * 12 + 8];
                ull gp[8];
                gp[0] = pk2(g0.x); gp[1] = pk2(g0.y); gp[2] = pk2(g0.z); gp[3] = pk2(g0.w);
                gp[4] = pk2(g1.x); gp[5] = pk2(g1.y); gp[6] = pk2(g1.z); gp[7] = pk2(g1.w);
                #pragma unroll
                for (int i = 0; i < 8; ++i) {
                    fma2(acc[i][0], gp[i], w0.x);
                    fma2(acc[i][1], gp[i], w0.y);
                    fma2(acc[i][2], gp[i], w1.x);
                    fma2(acc[i][3], gp[i], w1.y);
                    fma2(acc[i][4], gp[i], w2.x);
                    fma2(acc[i][5], gp[i], w2.y);
                }
            }
            __syncthreads();
        }

        #pragma unroll
        for (int i = 0; i < 8; ++i) {
            int q = ty * 8 + i;
            const float* tirow = &ti[((long)(b * 512 + q0 + q)) * 96 + tx * 12];
            float s = 0.f;
            #pragma unroll
            for (int j = 0; j < 6; ++j) {
                int m = tx * 12 + 2 * j;
                float2 a = up2(acc[i][j]);
                float2 t = *(const float2*)&tirow[2 * j];
                float h0 = fmaxf(a.x + tjb_s[m] + t.x, 0.f);
                float h1 = fmaxf(a.y + tjb_s[m + 1] + t.y, 0.f);
                s = fmaf(h0, ws2_s[m], s);
                s = fmaf(h1, ws2_s[m + 1], s);
            }
            s += __shfl_xor_sync(0xffffffffu, s, 1);
            s += __shfl_xor_sync(0xffffffffu, s, 2);
            s += __shfl_xor_sync(0xffffffffu, s, 4);
            if (tx == 0) logits_s[q0 + q] = s;
        }
    }
    __syncthreads();

    const float bs2v = *bs2;
    #pragma unroll
    for (int q = tid; q < 512; q += 128) {
        float mv = (float)attn_mask[b * 512 + q];
        logits_s[q] += bs2v + (1.f - mv) * (-3.402823466e38f);
    }
    __syncthreads();

    const int wid = tid >> 5, lane = tid & 31;
    float lmax = -INFINITY;
    #pragma unroll
    for (int q = tid; q < 512; q += 128) lmax = fmaxf(lmax, logits_s[q]);
    #pragma unroll
    for (int o = 16; o > 0; o >>= 1) lmax = fmaxf(lmax, __shfl_xor_sync(0xffffffffu, lmax, o));
    if (lane == 0) red_s[wid] = lmax;
    __syncthreads();
    lmax = fmaxf(fmaxf(red_s[0], red_s[1]), fmaxf(red_s[2], red_s[3]));

    float lsum = 0.f;
    float ev[4];
    #pragma unroll
    for (int u = 0; u < 4; ++u) {
        int q = tid + u * 128;
        ev[u] = expf(logits_s[q] - lmax);
        lsum += ev[u];
    }
    #pragma unroll
    for (int o = 16; o > 0; o >>= 1) lsum += __shfl_xor_sync(0xffffffffu, lsum, o);
    if (lane == 0) red_s[4 + wid] = lsum;
    __syncthreads();
    const float inv = 1.f / (red_s[4] + red_s[5] + red_s[6] + red_s[7]);
    #pragma unroll
    for (int u = 0; u < 4; ++u) {
        int q = tid + u * 128;
        probs[(long)pg * 512 + q] = ev[u] * inv;
    }
}

// ---------------- launch ----------------
extern "C" void kernel_launch(void* const* d_in, const int* in_sizes, int n_in,
                              void* d_out, int out_size)
{
    const float* Hj   = (const float*)d_in[0];
    const float* Hi   = (const float*)d_in[1];
    const float* Wpj  = (const float*)d_in[2];
    const float* Wpi  = (const float*)d_in[3];
    const float* Ws1  = (const float*)d_in[4];
    const float* bs1  = (const float*)d_in[5];
    const float* ws2  = (const float*)d_in[6];
    const float* bs2  = (const float*)d_in[7];
    const float* Wv1  = (const float*)d_in[8];
    const float* bv1  = (const float*)d_in[9];
    const float* Wv2  = (const float*)d_in[10];
    const float* bv2  = (const float*)d_in[11];
    const float* alpha= (const float*)d_in[12];
    const int*   mask = (const int*)d_in[13];
    float* out = (float*)d_out;

    float *Zj, *Zi, *tjb, *ti, *probs, *ctx, *mhid;
    cudaGetSymbolAddress((void**)&Zj, g_Zj);
    cudaGetSymbolAddress((void**)&Zi, g_Zi);
    cudaGetSymbolAddress((void**)&tjb, g_tjb);
    cudaGetSymbolAddress((void**)&ti, g_ti);
    cudaGetSymbolAddress((void**)&probs, g_probs);
    cudaGetSymbolAddress((void**)&ctx, g_ctx);
    cudaGetSymbolAddress((void**)&mhid, g_mhid);

    // Zj = H_j @ Wpj ; Zi = H_i @ Wpi   (2048 x 24, K=768), batched
    sgemm_small2<<<dim3(1, ROWS/64, 2), 256>>>(
        Hj, Wpj, Zj, nullptr, Hi, Wpi, Zi, nullptr,
        ROWS, DD, HD, HD, DD, DD);

    // tjb = Zj @ Ws1[0:24] + bs1 ; ti = Zi @ Ws1[24:48]   (2048 x 96, K=24), batched
    sgemm_small2<<<dim3(2, ROWS/64, 2), 256>>>(
        Zj, Ws1, tjb, bs1, Zi, Ws1 + DD * MMDIM, ti, nullptr,
        ROWS, MMDIM, DD, DD, MMDIM, MMDIM);

    // fused pairwise logits + softmax -> probs
    pairwise_kernel<<<ROWS, 128>>>(Zj, Zi, tjb, ti, Ws1, ws2, bs2, mask, probs);

    // ctx = probs @ H_i   (batched 4x: 512 x 768, K=512)
    gemmv3<0,false,false,false><<<dim3(HD/64, SEQ/128, BATCH), 128>>>(
        probs, Hi, ctx, SEQ, SEQ, HD, HD, nullptr, nullptr,
        (long)SEQ*SEQ, (long)SEQ*HD, (long)SEQ*HD, nullptr, nullptr);

    // mhid = relu([ctx|Hj|ctx*Hj] @ Wv1 + bv1)   (2048 x 768, K=2304; X fused)
    gemmv3<1,true,true,false><<<dim3(OO/64, ROWS/128, 1), 128>>>(
        nullptr, Wv1, mhid, XCOLS, 0, OO, OO, bv1, nullptr,
        0, 0, 0, ctx, Hj);

    // out = alpha * (mhid @ Wv2 + bv2)   (2048 x 768, K=768)
    gemmv3<0,true,false,true><<<dim3(HD/64, ROWS/128, 1), 128>>>(
        mhid, Wv2, out, OO, OO, HD, HD, bv2, alpha,
        0, 0, 0, nullptr, nullptr);
}

// round 6
// speedup vs baseline: 1.1951x; 1.1934x over previous
#include <cuda_runtime.h>
#include <math.h>

#define BATCH 4
#define SEQ   512
#define HD    768
#define DD    24
#define MMDIM 96
#define OO    768
#define ROWS  (BATCH*SEQ)       // 2048
#define XCOLS (3*HD)            // 2304

typedef unsigned long long ull;

// ---------------- scratch (no allocations allowed) ----------------
__device__ float g_Zj[ROWS*DD];
__device__ float g_Zi[ROWS*DD];
__device__ float g_tjb[ROWS*MMDIM];
__device__ float g_ti[ROWS*MMDIM];
__device__ float g_probs[(long)BATCH*SEQ*SEQ];
__device__ float g_ctx[(long)ROWS*HD];
__device__ float g_mhid[(long)ROWS*OO];

// ---------------- packed f32x2 helpers ----------------
__device__ __forceinline__ ull pk2(float x) {
    ull r; asm("mov.b64 %0, {%1, %1};" : "=l"(r) : "f"(x)); return r;
}
__device__ __forceinline__ void fma2(ull &d, ull a, ull b) {
    asm("fma.rn.f32x2 %0, %1, %2, %0;" : "+l"(d) : "l"(a), "l"(b));
}
__device__ __forceinline__ float2 up2(ull v) {
    float2 r; asm("mov.b64 {%0, %1}, %2;" : "=f"(r.x), "=f"(r.y) : "l"(v)); return r;
}

// ---------------- small generic SGEMM, z-batched over pointer pairs ----------------
__global__ __launch_bounds__(256)
void sgemm_small2(const float* __restrict__ A0, const float* __restrict__ B0,
                  float* __restrict__ C0, const float* __restrict__ bias0,
                  const float* __restrict__ A1, const float* __restrict__ B1,
                  float* __restrict__ C1, const float* __restrict__ bias1,
                  int M, int N, int K, int lda, int ldb, int ldc)
{
    __shared__ float As[16][64];
    __shared__ float Bs[16][64];
    const float* A = blockIdx.z ? A1 : A0;
    const float* B = blockIdx.z ? B1 : B0;
    float*       C = blockIdx.z ? C1 : C0;
    const float* bias = blockIdx.z ? bias1 : bias0;

    const int tid = threadIdx.x;
    const int tx = tid & 15, ty = tid >> 4;
    const int row0 = blockIdx.y * 64;
    const int col0 = blockIdx.x * 64;

    float acc[4][4] = {};
    for (int k0 = 0; k0 < K; k0 += 16) {
        #pragma unroll
        for (int u = 0; u < 4; ++u) {
            int t = tid + u * 256;
            int r = t >> 4, kk = t & 15;
            int gr = row0 + r, gk = k0 + kk;
            float v = 0.f;
            if (gr < M && gk < K) v = A[(long)gr * lda + gk];
            As[kk][r] = v;
        }
        #pragma unroll
        for (int u = 0; u < 4; ++u) {
            int t = tid + u * 256;
            int kk = t >> 6, n = t & 63;
            int gk = k0 + kk, gn = col0 + n;
            float v = 0.f;
            if (gk < K && gn < N) v = B[(long)gk * ldb + gn];
            Bs[kk][n] = v;
        }
        __syncthreads();
        #pragma unroll
        for (int kk = 0; kk < 16; ++kk) {
            float4 a4 = *(const float4*)&As[kk][ty * 4];
            float4 b4 = *(const float4*)&Bs[kk][tx * 4];
            float a[4] = {a4.x, a4.y, a4.z, a4.w};
            float b[4] = {b4.x, b4.y, b4.z, b4.w};
            #pragma unroll
            for (int i = 0; i < 4; ++i)
                #pragma unroll
                for (int j = 0; j < 4; ++j)
                    acc[i][j] = fmaf(a[i], b[j], acc[i][j]);
        }
        __syncthreads();
    }
    #pragma unroll
    for (int i = 0; i < 4; ++i) {
        int r = row0 + ty * 4 + i;
        if (r >= M) continue;
        #pragma unroll
        for (int j = 0; j < 4; ++j) {
            int c = col0 + tx * 4 + j;
            if (c >= N) continue;
            float v = acc[i][j];
            if (bias) v += bias[c];
            C[(long)r * ldc + c] = v;
        }
    }
}

// ---------------- gemmks: 64x64 tile, 256 threads, intra-block split-K x2 ----------------
// Each 128-thread k-group runs an 8x4 microtile over half of each 32-k tile.
// Double-buffered smem (1 sync/tile); smem reduction + kg0 epilogue at the end.
// Exact-multiple dims (K % 32 == 0), unguarded.
// AMODE 0: plain A. AMODE 1: A = [ctx | Hj | ctx*Hj] generated on the fly.
template<int AMODE, bool BIAS, bool RELU, bool SCALE>
__global__ __launch_bounds__(256)
void gemmks(const float* __restrict__ A, const float* __restrict__ B,
            float* __restrict__ C, int K, int lda, int ldb, int ldc,
            const float* __restrict__ bias, const float* __restrict__ alpha_ptr,
            long sA, long sB, long sC,
            const float* __restrict__ Actx, const float* __restrict__ Ahj)
{
    __shared__ float As[2][32][68];   // [buf][k][row]
    __shared__ float Bs[2][32][68];   // [buf][k][col]

    const int bz = blockIdx.z;
    if (AMODE == 0) A += (long)bz * sA;
    B += (long)bz * sB;  C += (long)bz * sC;

    const int tid = threadIdx.x;
    const int kg = tid >> 7;           // k-group 0/1
    const int lt = tid & 127;
    const int tx = lt & 15;            // 16 col groups x 4 cols
    const int ty = lt >> 4;            // 8 row groups x 8 rows
    const int row0 = blockIdx.y * 64;
    const int col0 = blockIdx.x * 64;

    ull acc[8][2];
    #pragma unroll
    for (int i = 0; i < 8; ++i) { acc[i][0] = 0ull; acc[i][1] = 0ull; }

    float4 pa[2], pb[2];

    // A tile: 64 rows x 32 k = 512 float4; thread u-pass: lin = tid + u*256
    auto loadA = [&](int kt) {
        #pragma unroll
        for (int u = 0; u < 2; ++u) {
            int lin = tid + u * 256;
            int r = lin >> 3, kc = lin & 7;
            int gk = kt + kc * 4;
            if (AMODE == 0) {
                pa[u] = *(const float4*)&A[(long)(row0 + r) * lda + gk];
            } else {
                long ridx = (long)(row0 + r) * HD;
                if (gk < HD) {
                    pa[u] = *(const float4*)&Actx[ridx + gk];
                } else if (gk < 2 * HD) {
                    pa[u] = *(const float4*)&Ahj[ridx + gk - HD];
                } else {
                    float4 c4 = *(const float4*)&Actx[ridx + gk - 2 * HD];
                    float4 h4 = *(const float4*)&Ahj[ridx + gk - 2 * HD];
                    pa[u].x = c4.x * h4.x; pa[u].y = c4.y * h4.y;
                    pa[u].z = c4.z * h4.z; pa[u].w = c4.w * h4.w;
                }
            }
        }
    };
    // B tile: 32 k x 64 n = 512 float4
    auto loadB = [&](int kt) {
        #pragma unroll
        for (int u = 0; u < 2; ++u) {
            int lin = tid + u * 256;
            int bkr = lin >> 4, bn4 = lin & 15;
            pb[u] = *(const float4*)&B[(long)(kt + bkr) * ldb + col0 + bn4 * 4];
        }
    };
    auto storeTiles = [&](int buf) {
        #pragma unroll
        for (int u = 0; u < 2; ++u) {
            int lin = tid + u * 256;
            int r = lin >> 3, kc = lin & 7;
            As[buf][kc * 4 + 0][r] = pa[u].x;
            As[buf][kc * 4 + 1][r] = pa[u].y;
            As[buf][kc * 4 + 2][r] = pa[u].z;
            As[buf][kc * 4 + 3][r] = pa[u].w;
            int bkr = lin >> 4, bn4 = lin & 15;
            *(float4*)&Bs[buf][bkr][bn4 * 4] = pb[u];
        }
    };

    loadA(0); loadB(0);
    storeTiles(0);
    __syncthreads();

    int cur = 0;
    for (int kt = 0; kt < K; kt += 32) {
        const bool more = (kt + 32) < K;
        if (more) { loadA(kt + 32); loadB(kt + 32); }

        #pragma unroll
        for (int kk = 0; kk < 16; ++kk) {
            const int k = kg * 16 + kk;
            float4 a0 = *(const float4*)&As[cur][k][ty * 8];
            float4 a1 = *(const float4*)&As[cur][k][ty * 8 + 4];
            ulonglong2 bl = *(const ulonglong2*)&Bs[cur][k][tx * 4];
            ull ap[8];
            ap[0] = pk2(a0.x); ap[1] = pk2(a0.y); ap[2] = pk2(a0.z); ap[3] = pk2(a0.w);
            ap[4] = pk2(a1.x); ap[5] = pk2(a1.y); ap[6] = pk2(a1.z); ap[7] = pk2(a1.w);
            #pragma unroll
            for (int i = 0; i < 8; ++i) {
                fma2(acc[i][0], ap[i], bl.x);
                fma2(acc[i][1], ap[i], bl.y);
            }
        }
        if (more) {
            storeTiles(cur ^ 1);
        }
        __syncthreads();
        if (more) cur ^= 1;
    }

    // ---- cross-kg reduction via smem (reuse As; 128 thr x 16 ull = 16 KB) ----
    ull* redU = (ull*)&As[0][0][0];
    if (kg == 1) {
        #pragma unroll
        for (int i = 0; i < 8; ++i) {
            redU[lt * 16 + i * 2 + 0] = acc[i][0];
            redU[lt * 16 + i * 2 + 1] = acc[i][1];
        }
    }
    __syncthreads();
    if (kg != 0) return;

    float alpha = 1.f;
    if (SCALE) alpha = *alpha_ptr;
    float4 bv;
    if (BIAS) bv = *(const float4*)&bias[col0 + tx * 4];

    #pragma unroll
    for (int i = 0; i < 8; ++i) {
        int r = row0 + ty * 8 + i;
        int c = col0 + tx * 4;
        float2 o0 = up2(acc[i][0]);
        float2 o1 = up2(acc[i][1]);
        float2 p0 = up2(redU[lt * 16 + i * 2 + 0]);
        float2 p1 = up2(redU[lt * 16 + i * 2 + 1]);
        float4 v = make_float4(o0.x + p0.x, o0.y + p0.y, o1.x + p1.x, o1.y + p1.y);
        if (BIAS) { v.x += bv.x; v.y += bv.y; v.z += bv.z; v.w += bv.w; }
        if (RELU) {
            v.x = fmaxf(v.x, 0.f); v.y = fmaxf(v.y, 0.f);
            v.z = fmaxf(v.z, 0.f); v.w = fmaxf(v.w, 0.f);
        }
        v.x *= alpha; v.y *= alpha; v.z *= alpha; v.w *= alpha;
        *(float4*)&C[(long)r * ldc + c] = v;
    }
}

// ---------------- fused pairwise logits + softmax (FFMA2) — R3 version ----------------
__global__ __launch_bounds__(128)
void pairwise_kernel(const float* __restrict__ Zj, const float* __restrict__ Zi,
                     const float* __restrict__ tjb, const float* __restrict__ ti,
                     const float* __restrict__ Ws1, const float* __restrict__ ws2,
                     const float* __restrict__ bs2, const int* __restrict__ attn_mask,
                     float* __restrict__ probs)
{
    __shared__ float Wc_s[48][96];
    __shared__ float Gs[24][128];
    __shared__ float Zis[128][25];
    __shared__ float logits_s[512];
    __shared__ float Zjp_s[24];
    __shared__ float tjb_s[96];
    __shared__ float ws2_s[96];
    __shared__ float red_s[8];

    const int tid = threadIdx.x;
    const int tx = tid & 7;
    const int ty = tid >> 3;
    const int pg = blockIdx.x;
    const int b = pg >> 9;

    for (int idx = tid; idx < 48 * 96; idx += 128)
        (&Wc_s[0][0])[idx] = Ws1[48 * 96 + idx];
    if (tid < 24) Zjp_s[tid] = Zj[pg * 24 + tid];
    if (tid < 96) { tjb_s[tid] = tjb[pg * 96 + tid]; ws2_s[tid] = ws2[tid]; }
    __syncthreads();

    #pragma unroll 1
    for (int qt = 0; qt < 4; ++qt) {
        const int q0 = qt * 128;
        for (int idx = tid; idx < 128 * 24; idx += 128) {
            int q = idx / 24, d = idx - q * 24;
            Zis[q][d] = Zi[((long)(b * 512 + q0 + q)) * 24 + d];
        }
        __syncthreads();

        ull acc[8][6];
        #pragma unroll
        for (int i = 0; i < 8; ++i)
            #pragma unroll
            for (int j = 0; j < 6; ++j) acc[i][j] = 0ull;

        #pragma unroll 1
        for (int ph = 0; ph < 2; ++ph) {
            for (int idx = tid; idx < 24 * 128; idx += 128) {
                int k = idx >> 7, q = idx & 127;
                float zj = Zjp_s[k], zi = Zis[q][k];
                Gs[k][q] = ph ? fabsf(zj - zi) : zj * zi;
            }
            __syncthreads();
            const int kbase = ph * 24;
            #pragma unroll
            for (int k = 0; k < 24; ++k) {
                float4 g0 = *(const float4*)&Gs[k][ty * 8];
                float4 g1 = *(const float4*)&Gs[k][ty * 8 + 4];
                ulonglong2 w0 = *(const ulonglong2*)&Wc_s[kbase + k][tx * 12];
                ulonglong2 w1 = *(const ulonglong2*)&Wc_s[kbase + k][tx * 12 + 4];
                ulonglong2 w2 = *(const ulonglong2*)&Wc_s[kbase + k][tx * 12 + 8];
                ull gp[8];
                gp[0] = pk2(g0.x); gp[1] = pk2(g0.y); gp[2] = pk2(g0.z); gp[3] = pk2(g0.w);
                gp[4] = pk2(g1.x); gp[5] = pk2(g1.y); gp[6] = pk2(g1.z); gp[7] = pk2(g1.w);
                #pragma unroll
                for (int i = 0; i < 8; ++i) {
                    fma2(acc[i][0], gp[i], w0.x);
                    fma2(acc[i][1], gp[i], w0.y);
                    fma2(acc[i][2], gp[i], w1.x);
                    fma2(acc[i][3], gp[i], w1.y);
                    fma2(acc[i][4], gp[i], w2.x);
                    fma2(acc[i][5], gp[i], w2.y);
                }
            }
            __syncthreads();
        }

        #pragma unroll
        for (int i = 0; i < 8; ++i) {
            int q = ty * 8 + i;
            const float* tirow = &ti[((long)(b * 512 + q0 + q)) * 96 + tx * 12];
            float s = 0.f;
            #pragma unroll
            for (int j = 0; j < 6; ++j) {
                int m = tx * 12 + 2 * j;
                float2 a = up2(acc[i][j]);
                float2 t = *(const float2*)&tirow[2 * j];
                float h0 = fmaxf(a.x + tjb_s[m] + t.x, 0.f);
                float h1 = fmaxf(a.y + tjb_s[m + 1] + t.y, 0.f);
                s = fmaf(h0, ws2_s[m], s);
                s = fmaf(h1, ws2_s[m + 1], s);
            }
            s += __shfl_xor_sync(0xffffffffu, s, 1);
            s += __shfl_xor_sync(0xffffffffu, s, 2);
            s += __shfl_xor_sync(0xffffffffu, s, 4);
            if (tx == 0) logits_s[q0 + q] = s;
        }
    }
    __syncthreads();

    const float bs2v = *bs2;
    #pragma unroll
    for (int q = tid; q < 512; q += 128) {
        float mv = (float)attn_mask[b * 512 + q];
        logits_s[q] += bs2v + (1.f - mv) * (-3.402823466e38f);
    }
    __syncthreads();

    const int wid = tid >> 5, lane = tid & 31;
    float lmax = -INFINITY;
    #pragma unroll
    for (int q = tid; q < 512; q += 128) lmax = fmaxf(lmax, logits_s[q]);
    #pragma unroll
    for (int o = 16; o > 0; o >>= 1) lmax = fmaxf(lmax, __shfl_xor_sync(0xffffffffu, lmax, o));
    if (lane == 0) red_s[wid] = lmax;
    __syncthreads();
    lmax = fmaxf(fmaxf(red_s[0], red_s[1]), fmaxf(red_s[2], red_s[3]));

    float lsum = 0.f;
    float ev[4];
    #pragma unroll
    for (int u = 0; u < 4; ++u) {
        int q = tid + u * 128;
        ev[u] = expf(logits_s[q] - lmax);
        lsum += ev[u];
    }
    #pragma unroll
    for (int o = 16; o > 0; o >>= 1) lsum += __shfl_xor_sync(0xffffffffu, lsum, o);
    if (lane == 0) red_s[4 + wid] = lsum;
    __syncthreads();
    const float inv = 1.f / (red_s[4] + red_s[5] + red_s[6] + red_s[7]);
    #pragma unroll
    for (int u = 0; u < 4; ++u) {
        int q = tid + u * 128;
        probs[(long)pg * 512 + q] = ev[u] * inv;
    }
}

// ---------------- launch ----------------
extern "C" void kernel_launch(void* const* d_in, const int* in_sizes, int n_in,
                              void* d_out, int out_size)
{
    const float* Hj   = (const float*)d_in[0];
    const float* Hi   = (const float*)d_in[1];
    const float* Wpj  = (const float*)d_in[2];
    const float* Wpi  = (const float*)d_in[3];
    const float* Ws1  = (const float*)d_in[4];
    const float* bs1  = (const float*)d_in[5];
    const float* ws2  = (const float*)d_in[6];
    const float* bs2  = (const float*)d_in[7];
    const float* Wv1  = (const float*)d_in[8];
    const float* bv1  = (const float*)d_in[9];
    const float* Wv2  = (const float*)d_in[10];
    const float* bv2  = (const float*)d_in[11];
    const float* alpha= (const float*)d_in[12];
    const int*   mask = (const int*)d_in[13];
    float* out = (float*)d_out;

    float *Zj, *Zi, *tjb, *ti, *probs, *ctx, *mhid;
    cudaGetSymbolAddress((void**)&Zj, g_Zj);
    cudaGetSymbolAddress((void**)&Zi, g_Zi);
    cudaGetSymbolAddress((void**)&tjb, g_tjb);
    cudaGetSymbolAddress((void**)&ti, g_ti);
    cudaGetSymbolAddress((void**)&probs, g_probs);
    cudaGetSymbolAddress((void**)&ctx, g_ctx);
    cudaGetSymbolAddress((void**)&mhid, g_mhid);

    // Zj = H_j @ Wpj ; Zi = H_i @ Wpi   (2048 x 24, K=768), batched
    sgemm_small2<<<dim3(1, ROWS/64, 2), 256>>>(
        Hj, Wpj, Zj, nullptr, Hi, Wpi, Zi, nullptr,
        ROWS, DD, HD, HD, DD, DD);

    // tjb = Zj @ Ws1[0:24] + bs1 ; ti = Zi @ Ws1[24:48]   (2048 x 96, K=24), batched
    sgemm_small2<<<dim3(2, ROWS/64, 2), 256>>>(
        Zj, Ws1, tjb, bs1, Zi, Ws1 + DD * MMDIM, ti, nullptr,
        ROWS, MMDIM, DD, DD, MMDIM, MMDIM);

    // fused pairwise logits + softmax -> probs
    pairwise_kernel<<<ROWS, 128>>>(Zj, Zi, tjb, ti, Ws1, ws2, bs2, mask, probs);

    // ctx = probs @ H_i   (batched 4x: 512 x 768, K=512)
    gemmks<0,false,false,false><<<dim3(HD/64, SEQ/64, BATCH), 256>>>(
        probs, Hi, ctx, SEQ, SEQ, HD, HD, nullptr, nullptr,
        (long)SEQ*SEQ, (long)SEQ*HD, (long)SEQ*HD, nullptr, nullptr);

    // mhid = relu([ctx|Hj|ctx*Hj] @ Wv1 + bv1)   (2048 x 768, K=2304; X fused)
    gemmks<1,true,true,false><<<dim3(OO/64, ROWS/64, 1), 256>>>(
        nullptr, Wv1, mhid, XCOLS, 0, OO, OO, bv1, nullptr,
        0, 0, 0, ctx, Hj);

    // out = alpha * (mhid @ Wv2 + bv2)   (2048 x 768, K=768)
    gemmks<0,true,false,true><<<dim3(HD/64, ROWS/64, 1), 256>>>(
        mhid, Wv2, out, OO, OO, HD, HD, bv2, alpha,
        0, 0, 0, nullptr, nullptr);
}